// round 1
// baseline (speedup 1.0000x reference)
#include <cuda_runtime.h>
#include <math.h>

// ContrastiveLoss (NT-Xent), N=4096, D=1024, T=0.5
// Pipeline:
//   1) normalize_kernel: L2-normalize rows of emb_i/emb_j into g_z [8192,1024] (also zeroes accumulators)
//   2) simloss_kernel:  fused z·z^T GEMM; per tile computes exp(sim/T) row-sums (excluding diag)
//                       and captures the positive-pair similarity. Never materializes sim.
//   3) loss_kernel:     per-row log(denom) - pos/T, block-reduced, atomicAdd into g_loss
//   4) final_kernel:    out[0] = g_loss / 8192

#define TWO_N 8192
#define NHALF 4096
#define DIM   1024
#define INV_T 2.0f

// Scratch (static __device__ globals per harness rules)
__device__ float g_z[(size_t)TWO_N * DIM];   // normalized embeddings, 32 MB (fits L2)
__device__ float g_denom[TWO_N];
__device__ float g_pos[TWO_N];
__device__ float g_loss;

// ---------------------------------------------------------------------------
// 1) Row L2-normalize. One block per row, 256 threads, one float4 each.
// ---------------------------------------------------------------------------
__global__ __launch_bounds__(256) void normalize_kernel(const float* __restrict__ ei,
                                                        const float* __restrict__ ej) {
    const int row = blockIdx.x;
    const int t   = threadIdx.x;
    const float* src = (row < NHALF) ? (ei + (size_t)row * DIM)
                                     : (ej + (size_t)(row - NHALF) * DIM);
    float4 x = ((const float4*)src)[t];
    float s = x.x * x.x + x.y * x.y + x.z * x.z + x.w * x.w;
#pragma unroll
    for (int o = 16; o > 0; o >>= 1) s += __shfl_xor_sync(0xffffffffu, s, o);

    __shared__ float ws[8];
    if ((t & 31) == 0) ws[t >> 5] = s;
    __syncthreads();
    float tot = ws[0] + ws[1] + ws[2] + ws[3] + ws[4] + ws[5] + ws[6] + ws[7];

    float inv = 1.0f / fmaxf(sqrtf(tot), 1e-12f);
    float4 o4 = make_float4(x.x * inv, x.y * inv, x.z * inv, x.w * inv);
    ((float4*)(g_z + (size_t)row * DIM))[t] = o4;

    if (t == 0) {
        g_denom[row] = 0.0f;
        if (row == 0) g_loss = 0.0f;
    }
}

// ---------------------------------------------------------------------------
// 2) Fused similarity GEMM + exp-rowsum epilogue.
//    Grid: (64 row-tiles of 128, 2 key-splits of 4096 cols) = 128 CTAs.
//    Block: 256 threads (16x16), each computes an 8x8 microtile.
//    Shared: As/Bs transposed [BK=16][128(+4 pad)].
// ---------------------------------------------------------------------------
__global__ __launch_bounds__(256) void simloss_kernel() {
    const int t  = threadIdx.x;
    const int tx = t & 15;
    const int ty = t >> 4;
    const int row0    = blockIdx.x * 128;
    const int colbase = blockIdx.y * 4096;

    __shared__ __align__(16) float As[16][132];
    __shared__ __align__(16) float Bs[16][132];

    float rp[8];
#pragma unroll
    for (int i = 0; i < 8; i++) rp[i] = 0.0f;

    for (int jt = 0; jt < 4096; jt += 128) {
        const int col0 = colbase + jt;

        float acc[8][8];
#pragma unroll
        for (int i = 0; i < 8; i++)
#pragma unroll
            for (int j = 0; j < 8; j++) acc[i][j] = 0.0f;

        for (int k0 = 0; k0 < DIM; k0 += 16) {
            // Load 128x16 A and B tiles, transposed into shared.
#pragma unroll
            for (int l = 0; l < 2; l++) {
                int idx = t + l * 256;       // 0..511 float4 units
                int m   = idx >> 2;          // 0..127
                int kq  = (idx & 3) << 2;    // 0,4,8,12
                float4 va = *(const float4*)&g_z[(size_t)(row0 + m) * DIM + k0 + kq];
                As[kq + 0][m] = va.x; As[kq + 1][m] = va.y;
                As[kq + 2][m] = va.z; As[kq + 3][m] = va.w;
                float4 vb = *(const float4*)&g_z[(size_t)(col0 + m) * DIM + k0 + kq];
                Bs[kq + 0][m] = vb.x; Bs[kq + 1][m] = vb.y;
                Bs[kq + 2][m] = vb.z; Bs[kq + 3][m] = vb.w;
            }
            __syncthreads();

#pragma unroll
            for (int k = 0; k < 16; k++) {
                float a[8], b[8];
                float4 a0 = *(const float4*)&As[k][ty * 8];
                float4 a1 = *(const float4*)&As[k][ty * 8 + 4];
                a[0] = a0.x; a[1] = a0.y; a[2] = a0.z; a[3] = a0.w;
                a[4] = a1.x; a[5] = a1.y; a[6] = a1.z; a[7] = a1.w;
                float4 b0 = *(const float4*)&Bs[k][tx * 8];
                float4 b1 = *(const float4*)&Bs[k][tx * 8 + 4];
                b[0] = b0.x; b[1] = b0.y; b[2] = b0.z; b[3] = b0.w;
                b[4] = b1.x; b[5] = b1.y; b[6] = b1.z; b[7] = b1.w;
#pragma unroll
                for (int i = 0; i < 8; i++)
#pragma unroll
                    for (int j = 0; j < 8; j++) acc[i][j] = fmaf(a[i], b[j], acc[i][j]);
            }
            __syncthreads();
        }

        // Epilogue on the 128x128 sim tile: exp rowsum (skip diag), grab positive.
#pragma unroll
        for (int i = 0; i < 8; i++) {
            int r    = row0 + ty * 8 + i;
            int pcol = (r < NHALF) ? (r + NHALF) : (r - NHALF);
#pragma unroll
            for (int j = 0; j < 8; j++) {
                int   c = col0 + tx * 8 + j;
                float s = acc[i][j];
                if (c == r) continue;              // mask self-similarity
                rp[i] += __expf(s * INV_T);
                if (c == pcol) g_pos[r] = s;       // unique writer per row
            }
        }
    }

#pragma unroll
    for (int i = 0; i < 8; i++) atomicAdd(&g_denom[row0 + ty * 8 + i], rp[i]);
}

// ---------------------------------------------------------------------------
// 3) Per-row loss, reduced to g_loss.
// ---------------------------------------------------------------------------
__global__ __launch_bounds__(256) void loss_kernel() {
    const int r = blockIdx.x * 256 + threadIdx.x;
    float v = 0.0f;
    if (r < TWO_N) v = logf(g_denom[r]) - g_pos[r] * INV_T;
#pragma unroll
    for (int o = 16; o > 0; o >>= 1) v += __shfl_xor_sync(0xffffffffu, v, o);
    __shared__ float ws[8];
    if ((threadIdx.x & 31) == 0) ws[threadIdx.x >> 5] = v;
    __syncthreads();
    if (threadIdx.x == 0) {
        float s = ws[0] + ws[1] + ws[2] + ws[3] + ws[4] + ws[5] + ws[6] + ws[7];
        atomicAdd(&g_loss, s);
    }
}

__global__ void final_kernel(float* out) {
    out[0] = g_loss * (1.0f / (float)TWO_N);
}

// ---------------------------------------------------------------------------
extern "C" void kernel_launch(void* const* d_in, const int* in_sizes, int n_in,
                              void* d_out, int out_size) {
    const float* emb_i = (const float*)d_in[0];
    const float* emb_j = (const float*)d_in[1];
    float* out = (float*)d_out;

    normalize_kernel<<<TWO_N, 256>>>(emb_i, emb_j);
    dim3 grid(64, 2);
    simloss_kernel<<<grid, 256>>>();
    loss_kernel<<<TWO_N / 256, 256>>>();
    final_kernel<<<1, 1>>>(out);
}

// round 3
// speedup vs baseline: 9.9583x; 9.9583x over previous
#include <cuda_runtime.h>
#include <cuda_bf16.h>
#include <cstdint>
#include <math.h>

// NT-Xent contrastive loss, N=4096, D=1024, T=0.5 — bf16 HMMA (mma.sync) fused version.
// (tcgen05 is unavailable: harness PTX target is compute_103, not compute_103a.)
//  1) normalize_kernel : L2-normalize rows -> g_zb (bf16 [8192,1024]), zero accumulators
//  2) simloss_kernel   : pipelined cp.async + ldmatrix + mma.sync z·z^T with fused
//                        exp-rowsum epilogue (diag masked) + positive capture
//  3) loss_kernel      : per-row log(denom) - 2*pos, reduce
//  4) final_kernel     : out[0] = loss / 8192

#define TWO_N 8192
#define NHALF 4096
#define DIM   1024
#define INV_T 2.0f

__device__ __nv_bfloat16 g_zb[(size_t)TWO_N * DIM];
__device__ float g_denom[TWO_N];
__device__ float g_pos[TWO_N];
__device__ float g_loss;

// ---------------------------------------------------------------- helpers
__device__ __forceinline__ uint32_t smem_u32(const void* p) {
    uint32_t a;
    asm("{ .reg .u64 t; cvta.to.shared.u64 t, %1; cvt.u32.u64 %0, t; }" : "=r"(a) : "l"(p));
    return a;
}

#define CP_ASYNC16(dst, src) \
    asm volatile("cp.async.cg.shared.global [%0], [%1], 16;" :: "r"(dst), "l"(src) : "memory")
#define CP_COMMIT() asm volatile("cp.async.commit_group;" ::: "memory")
#define CP_WAIT(n)  asm volatile("cp.async.wait_group %0;" :: "n"(n) : "memory")

__device__ __forceinline__ void ldsm4(uint32_t* r, uint32_t addr) {
    asm volatile("ldmatrix.sync.aligned.m8n8.x4.shared.b16 {%0,%1,%2,%3}, [%4];"
                 : "=r"(r[0]), "=r"(r[1]), "=r"(r[2]), "=r"(r[3]) : "r"(addr));
}

__device__ __forceinline__ void mma16816(float* c, const uint32_t* a, const uint32_t* b) {
    asm volatile("mma.sync.aligned.m16n8k16.row.col.f32.bf16.bf16.f32 "
                 "{%0,%1,%2,%3}, {%4,%5,%6,%7}, {%8,%9}, {%0,%1,%2,%3};"
                 : "+f"(c[0]), "+f"(c[1]), "+f"(c[2]), "+f"(c[3])
                 : "r"(a[0]), "r"(a[1]), "r"(a[2]), "r"(a[3]), "r"(b[0]), "r"(b[1]));
}

// Stage layout: A 128x64 bf16 (16KB) + B 256x64 bf16 (32KB), XOR-swizzled
// offset(row, ch16B) = row*128 + ((ch ^ (row&7)) * 16)
#define STAGE_BYTES 49152
#define AS_OFF(s)   ((s) * STAGE_BYTES)
#define BS_OFF(s)   ((s) * STAGE_BYTES + 16384)
#define SMEM_TOTAL  (3 * STAGE_BYTES)

// ---------------------------------------------------------------------------
__global__ __launch_bounds__(256) void normalize_kernel(const float* __restrict__ ei,
                                                        const float* __restrict__ ej) {
    const int row = blockIdx.x;
    const int t   = threadIdx.x;
    const float* src = (row < NHALF) ? (ei + (size_t)row * DIM)
                                     : (ej + (size_t)(row - NHALF) * DIM);
    float4 x = ((const float4*)src)[t];
    float s = x.x * x.x + x.y * x.y + x.z * x.z + x.w * x.w;
#pragma unroll
    for (int o = 16; o > 0; o >>= 1) s += __shfl_xor_sync(0xffffffffu, s, o);
    __shared__ float ws[8];
    if ((t & 31) == 0) ws[t >> 5] = s;
    __syncthreads();
    float tot = ws[0] + ws[1] + ws[2] + ws[3] + ws[4] + ws[5] + ws[6] + ws[7];
    float inv = 1.0f / fmaxf(sqrtf(tot), 1e-12f);

    __nv_bfloat162 a = __floats2bfloat162_rn(x.x * inv, x.y * inv);
    __nv_bfloat162 b = __floats2bfloat162_rn(x.z * inv, x.w * inv);
    uint32_t* dst = (uint32_t*)(g_zb + (size_t)row * DIM);
    dst[t * 2]     = *(uint32_t*)&a;
    dst[t * 2 + 1] = *(uint32_t*)&b;

    if (t == 0) {
        g_denom[row] = 0.0f;
        if (row == 0) g_loss = 0.0f;
    }
}

// ---------------------------------------------------------------------------
// Fused GEMM + loss. CTA tile 128x256 (8 warps as 2x4, warp tile 64x64).
// 3-stage cp.async pipeline over k chunks of 64.
// ---------------------------------------------------------------------------
__global__ __launch_bounds__(256, 1) void simloss_kernel() {
    extern __shared__ char smem[];
    const uint32_t sb = smem_u32(smem);
    const int tid  = threadIdx.x;
    const int wid  = tid >> 5;
    const int lane = tid & 31;
    const int wm   = wid >> 2;   // 0..1
    const int wn   = wid & 3;    // 0..3
    const int row0 = blockIdx.x * 128;
    const int col0 = blockIdx.y * 256;

    float acc[4][8][4];
#pragma unroll
    for (int mb = 0; mb < 4; mb++)
#pragma unroll
        for (int nb = 0; nb < 8; nb++)
#pragma unroll
            for (int q = 0; q < 4; q++) acc[mb][nb][q] = 0.0f;

    // ldmatrix lane address patterns (within stage, before k-chunk selection)
    // A (m16 x k16 per mb): lanes 0-15 rows m0-15 (chunk +0), 16-31 rows m0-15 (+1)
    const int a_row = lane & 15;
    const int a_sel = lane >> 4;
    // B (n16 x k16 per nb2): 0-7 n0-7(+0), 8-15 n0-7(+1), 16-23 n8-15(+0), 24-31 n8-15(+1)
    const int b_n   = (lane & 7) + ((lane >> 4) << 3);
    const int b_sel = (lane >> 3) & 1;

    // cp.async loader: 12 x 16B per thread per stage (A: 1024 chunks, B: 2048 chunks)
    auto load_stage = [&](int s, int kc) {
        const size_t k0 = (size_t)kc * 64;
#pragma unroll
        for (int i = 0; i < 12; i++) {
            int idx = tid + i * 256;
            uint32_t dst;
            const __nv_bfloat16* src;
            if (idx < 1024) {
                const int r = idx >> 3, ch = idx & 7;
                dst = sb + AS_OFF(s) + r * 128 + ((ch ^ (r & 7)) << 4);
                src = g_zb + (size_t)(row0 + r) * DIM + k0 + ch * 8;
            } else {
                const int j = idx - 1024;
                const int r = j >> 3, ch = j & 7;
                dst = sb + BS_OFF(s) + r * 128 + ((ch ^ (r & 7)) << 4);
                src = g_zb + (size_t)(col0 + r) * DIM + k0 + ch * 8;
            }
            CP_ASYNC16(dst, src);
        }
    };

    auto compute_stage = [&](int s) {
        const uint32_t as = sb + AS_OFF(s);
        const uint32_t bs = sb + BS_OFF(s);
#pragma unroll
        for (int kk = 0; kk < 4; kk++) {
            uint32_t a[4][4], b[4][4];
#pragma unroll
            for (int mb = 0; mb < 4; mb++) {
                const int r = wm * 64 + mb * 16 + a_row;
                const int ch = kk * 2 + a_sel;
                ldsm4(a[mb], as + r * 128 + ((ch ^ (r & 7)) << 4));
            }
#pragma unroll
            for (int nb2 = 0; nb2 < 4; nb2++) {
                const int r = wn * 64 + nb2 * 16 + b_n;
                const int ch = kk * 2 + b_sel;
                ldsm4(b[nb2], bs + r * 128 + ((ch ^ (r & 7)) << 4));
            }
#pragma unroll
            for (int mb = 0; mb < 4; mb++)
#pragma unroll
                for (int nb = 0; nb < 8; nb++)
                    mma16816(acc[mb][nb], a[mb], &b[nb >> 1][(nb & 1) * 2]);
        }
    };

    // Pipeline: 16 k-chunks, 3 stages
    load_stage(0, 0); CP_COMMIT();
    load_stage(1, 1); CP_COMMIT();
    CP_WAIT(1);
    __syncthreads();

    for (int ks = 0; ks < 16; ks++) {
        compute_stage(ks % 3);
        if (ks + 2 < 16) {
            load_stage((ks + 2) % 3, ks + 2);
            CP_COMMIT();
            CP_WAIT(1);
            __syncthreads();
        } else if (ks + 1 < 16) {
            CP_WAIT(0);
            __syncthreads();
        }
    }

    // ------------------------- epilogue -------------------------
    __syncthreads();
    float* red = (float*)smem;   // reuse stage memory
    if (tid < 128) red[tid] = 0.0f;
    __syncthreads();

#pragma unroll
    for (int mb = 0; mb < 4; mb++) {
        const int lrow = wm * 64 + mb * 16 + (lane >> 2);
        const int r_lo = row0 + lrow;
        const int r_hi = r_lo + 8;
        const int p_lo = (r_lo < NHALF) ? (r_lo + NHALF) : (r_lo - NHALF);
        const int p_hi = (r_hi < NHALF) ? (r_hi + NHALF) : (r_hi - NHALF);
        float slo = 0.0f, shi = 0.0f;
#pragma unroll
        for (int nb = 0; nb < 8; nb++) {
            const int c = col0 + wn * 64 + nb * 8 + (lane & 3) * 2;
            const float v0 = acc[mb][nb][0], v1 = acc[mb][nb][1];
            const float v2 = acc[mb][nb][2], v3 = acc[mb][nb][3];
            if (c     != r_lo) slo += __expf(v0 * INV_T);
            if (c + 1 != r_lo) slo += __expf(v1 * INV_T);
            if (c     != r_hi) shi += __expf(v2 * INV_T);
            if (c + 1 != r_hi) shi += __expf(v3 * INV_T);
            if (c     == p_lo) g_pos[r_lo] = v0;
            if (c + 1 == p_lo) g_pos[r_lo] = v1;
            if (c     == p_hi) g_pos[r_hi] = v2;
            if (c + 1 == p_hi) g_pos[r_hi] = v3;
        }
        slo += __shfl_xor_sync(0xffffffffu, slo, 1);
        slo += __shfl_xor_sync(0xffffffffu, slo, 2);
        shi += __shfl_xor_sync(0xffffffffu, shi, 1);
        shi += __shfl_xor_sync(0xffffffffu, shi, 2);
        if ((lane & 3) == 0) {
            atomicAdd(&red[lrow], slo);
            atomicAdd(&red[lrow + 8], shi);
        }
    }
    __syncthreads();
    if (tid < 128) atomicAdd(&g_denom[row0 + tid], red[tid]);
}

// ---------------------------------------------------------------------------
__global__ __launch_bounds__(256) void loss_kernel() {
    const int r = blockIdx.x * 256 + threadIdx.x;
    float v = 0.0f;
    if (r < TWO_N) v = logf(g_denom[r]) - g_pos[r] * INV_T;
#pragma unroll
    for (int o = 16; o > 0; o >>= 1) v += __shfl_xor_sync(0xffffffffu, v, o);
    __shared__ float ws[8];
    if ((threadIdx.x & 31) == 0) ws[threadIdx.x >> 5] = v;
    __syncthreads();
    if (threadIdx.x == 0) {
        float s = ws[0] + ws[1] + ws[2] + ws[3] + ws[4] + ws[5] + ws[6] + ws[7];
        atomicAdd(&g_loss, s);
    }
}

__global__ void final_kernel(float* out) {
    out[0] = g_loss * (1.0f / (float)TWO_N);
}

// ---------------------------------------------------------------------------
extern "C" void kernel_launch(void* const* d_in, const int* in_sizes, int n_in,
                              void* d_out, int out_size) {
    const float* emb_i = (const float*)d_in[0];
    const float* emb_j = (const float*)d_in[1];
    float* out = (float*)d_out;

    cudaFuncSetAttribute(simloss_kernel, cudaFuncAttributeMaxDynamicSharedMemorySize,
                         SMEM_TOTAL);

    normalize_kernel<<<TWO_N, 256>>>(emb_i, emb_j);
    dim3 grid(64, 32);
    simloss_kernel<<<grid, 256, SMEM_TOTAL>>>();
    loss_kernel<<<TWO_N / 256, 256>>>();
    final_kernel<<<1, 1>>>(out);
}

// round 5
// speedup vs baseline: 19.6212x; 1.9703x over previous
#include <cuda_runtime.h>
#include <cuda_bf16.h>
#include <cstdint>
#include <math.h>

// NT-Xent contrastive loss, N=4096, D=1024, T=0.5 — bf16 mma.sync, symmetric-half GEMM.
//  sim = z·z^T is symmetric: only tiles j>=i are computed (2080 of 4096).
//  Off-diagonal tiles contribute exp row-sums for BOTH their rows and (via column
//  sums) their columns. Positives (|r-c|=4096) captured for both orientations.

#define TWO_N 8192
#define NHALF 4096
#define DIM   1024
#define INV_T 2.0f

__device__ __nv_bfloat16 g_zb[(size_t)TWO_N * DIM];
__device__ float g_denom[TWO_N];
__device__ float g_pos[TWO_N];
__device__ float g_loss;

// ---------------------------------------------------------------- helpers
__device__ __forceinline__ uint32_t smem_u32(const void* p) {
    uint32_t a;
    asm("{ .reg .u64 t; cvta.to.shared.u64 t, %1; cvt.u32.u64 %0, t; }" : "=r"(a) : "l"(p));
    return a;
}

#define CP_ASYNC16(dst, src) \
    asm volatile("cp.async.cg.shared.global [%0], [%1], 16;" :: "r"(dst), "l"(src) : "memory")
#define CP_COMMIT() asm volatile("cp.async.commit_group;" ::: "memory")
#define CP_WAIT(n)  asm volatile("cp.async.wait_group %0;" :: "n"(n) : "memory")

__device__ __forceinline__ void ldsm4(uint32_t* r, uint32_t addr) {
    asm volatile("ldmatrix.sync.aligned.m8n8.x4.shared.b16 {%0,%1,%2,%3}, [%4];"
                 : "=r"(r[0]), "=r"(r[1]), "=r"(r[2]), "=r"(r[3]) : "r"(addr));
}

__device__ __forceinline__ void mma16816(float* c, const uint32_t* a, const uint32_t* b) {
    asm volatile("mma.sync.aligned.m16n8k16.row.col.f32.bf16.bf16.f32 "
                 "{%0,%1,%2,%3}, {%4,%5,%6,%7}, {%8,%9}, {%0,%1,%2,%3};"
                 : "+f"(c[0]), "+f"(c[1]), "+f"(c[2]), "+f"(c[3])
                 : "r"(a[0]), "r"(a[1]), "r"(a[2]), "r"(a[3]), "r"(b[0]), "r"(b[1]));
}

// Stage: A 128x64 bf16 (16KB) + B 128x64 bf16 (16KB), XOR swizzled (128B rows, 8x16B chunks)
#define STAGE_BYTES 32768
#define AS_OFF(s)   ((s) * STAGE_BYTES)
#define BS_OFF(s)   ((s) * STAGE_BYTES + 16384)
#define SMEM_TOTAL  (3 * STAGE_BYTES)

// ---------------------------------------------------------------------------
__global__ __launch_bounds__(256) void normalize_kernel(const float* __restrict__ ei,
                                                        const float* __restrict__ ej) {
    const int row = blockIdx.x;
    const int t   = threadIdx.x;
    const float* src = (row < NHALF) ? (ei + (size_t)row * DIM)
                                     : (ej + (size_t)(row - NHALF) * DIM);
    float4 x = ((const float4*)src)[t];
    float s = x.x * x.x + x.y * x.y + x.z * x.z + x.w * x.w;
#pragma unroll
    for (int o = 16; o > 0; o >>= 1) s += __shfl_xor_sync(0xffffffffu, s, o);
    __shared__ float ws[8];
    if ((t & 31) == 0) ws[t >> 5] = s;
    __syncthreads();
    float tot = ws[0] + ws[1] + ws[2] + ws[3] + ws[4] + ws[5] + ws[6] + ws[7];
    float inv = 1.0f / fmaxf(sqrtf(tot), 1e-12f);

    __nv_bfloat162 a = __floats2bfloat162_rn(x.x * inv, x.y * inv);
    __nv_bfloat162 b = __floats2bfloat162_rn(x.z * inv, x.w * inv);
    uint32_t* dst = (uint32_t*)(g_zb + (size_t)row * DIM);
    dst[t * 2]     = *(uint32_t*)&a;
    dst[t * 2 + 1] = *(uint32_t*)&b;

    if (t == 0) {
        g_denom[row] = 0.0f;
        if (row == 0) g_loss = 0.0f;
    }
}

// ---------------------------------------------------------------------------
// Symmetric fused GEMM+loss. Tile 128x128, 8 warps (2x4), warp tile 64x32.
// Grid 64x64; CTAs with col-tile < row-tile exit immediately.
// ---------------------------------------------------------------------------
__global__ __launch_bounds__(256, 2) void simloss_kernel() {
    const int ti = blockIdx.y;           // row tile
    const int tj = blockIdx.x;           // col tile
    if (tj < ti) return;
    const bool diag = (ti == tj);
    const int row0 = ti * 128;
    const int col0 = tj * 128;

    extern __shared__ char smem[];
    const uint32_t sb = smem_u32(smem);
    const int tid  = threadIdx.x;
    const int wid  = tid >> 5;
    const int lane = tid & 31;
    const int wm   = wid >> 2;   // 0..1  (64-row band)
    const int wn   = wid & 3;    // 0..3  (32-col band)

    float acc[4][4][4];
#pragma unroll
    for (int mb = 0; mb < 4; mb++)
#pragma unroll
        for (int nb = 0; nb < 4; nb++)
#pragma unroll
            for (int q = 0; q < 4; q++) acc[mb][nb][q] = 0.0f;

    const int a_row = lane & 15;
    const int a_sel = lane >> 4;
    const int b_n   = (lane & 7) + ((lane >> 4) << 3);
    const int b_sel = (lane >> 3) & 1;

    auto load_stage = [&](int s, int kc) {
        const size_t k0 = (size_t)kc * 64;
#pragma unroll
        for (int i = 0; i < 8; i++) {
            const int idx = tid + i * 256;
            if (idx < 1024) {
                const int r = idx >> 3, ch = idx & 7;
                CP_ASYNC16(sb + AS_OFF(s) + r * 128 + ((ch ^ (r & 7)) << 4),
                           g_zb + (size_t)(row0 + r) * DIM + k0 + ch * 8);
            } else if (!diag) {
                const int j = idx - 1024;
                const int r = j >> 3, ch = j & 7;
                CP_ASYNC16(sb + BS_OFF(s) + r * 128 + ((ch ^ (r & 7)) << 4),
                           g_zb + (size_t)(col0 + r) * DIM + k0 + ch * 8);
            }
        }
    };

    auto compute_stage = [&](int s) {
        const uint32_t as = sb + AS_OFF(s);
        const uint32_t bs = diag ? as : (sb + BS_OFF(s));
#pragma unroll
        for (int kk = 0; kk < 4; kk++) {
            uint32_t a[4][4], b[2][4];
#pragma unroll
            for (int mb = 0; mb < 4; mb++) {
                const int r = wm * 64 + mb * 16 + a_row;
                const int ch = kk * 2 + a_sel;
                ldsm4(a[mb], as + r * 128 + ((ch ^ (r & 7)) << 4));
            }
#pragma unroll
            for (int nb2 = 0; nb2 < 2; nb2++) {
                const int r = wn * 32 + nb2 * 16 + b_n;
                const int ch = kk * 2 + b_sel;
                ldsm4(b[nb2], bs + r * 128 + ((ch ^ (r & 7)) << 4));
            }
#pragma unroll
            for (int mb = 0; mb < 4; mb++)
#pragma unroll
                for (int nb = 0; nb < 4; nb++)
                    mma16816(acc[mb][nb], a[mb], &b[nb >> 1][(nb & 1) * 2]);
        }
    };

    load_stage(0, 0); CP_COMMIT();
    load_stage(1, 1); CP_COMMIT();
    CP_WAIT(1);
    __syncthreads();

    for (int ks = 0; ks < 16; ks++) {
        compute_stage(ks % 3);
        if (ks + 2 < 16) {
            load_stage((ks + 2) % 3, ks + 2);
            CP_COMMIT();
            CP_WAIT(1);
            __syncthreads();
        } else if (ks + 1 < 16) {
            CP_WAIT(0);
            __syncthreads();
        }
    }

    // ------------------------- epilogue -------------------------
    __syncthreads();
    float* rowred = (float*)smem;          // [128]
    float* colred = (float*)smem + 128;    // [128]
    if (tid < 128) { rowred[tid] = 0.0f; colred[tid] = 0.0f; }
    __syncthreads();

    float colacc[4][2];
#pragma unroll
    for (int nb = 0; nb < 4; nb++) colacc[nb][0] = colacc[nb][1] = 0.0f;

#pragma unroll
    for (int mb = 0; mb < 4; mb++) {
        const int lrow = wm * 64 + mb * 16 + (lane >> 2);
        const int r_lo = row0 + lrow;
        const int r_hi = r_lo + 8;
        const int p_lo = (r_lo < NHALF) ? (r_lo + NHALF) : (r_lo - NHALF);
        const int p_hi = (r_hi < NHALF) ? (r_hi + NHALF) : (r_hi - NHALF);
        float slo = 0.0f, shi = 0.0f;
#pragma unroll
        for (int nb = 0; nb < 4; nb++) {
            const int c = col0 + wn * 32 + nb * 8 + (lane & 3) * 2;
            const float v0 = acc[mb][nb][0], v1 = acc[mb][nb][1];
            const float v2 = acc[mb][nb][2], v3 = acc[mb][nb][3];
            float e0 = __expf(v0 * INV_T), e1 = __expf(v1 * INV_T);
            float e2 = __expf(v2 * INV_T), e3 = __expf(v3 * INV_T);
            if (diag) {
                if (c     == r_lo) e0 = 0.0f;
                if (c + 1 == r_lo) e1 = 0.0f;
                if (c     == r_hi) e2 = 0.0f;
                if (c + 1 == r_hi) e3 = 0.0f;
            } else {
                // positives live only in off-diagonal tiles; write both orientations
                if (c     == p_lo) { g_pos[r_lo] = v0; g_pos[c]     = v0; }
                if (c + 1 == p_lo) { g_pos[r_lo] = v1; g_pos[c + 1] = v1; }
                if (c     == p_hi) { g_pos[r_hi] = v2; g_pos[c]     = v2; }
                if (c + 1 == p_hi) { g_pos[r_hi] = v3; g_pos[c + 1] = v3; }
            }
            slo += e0 + e1;  shi += e2 + e3;
            colacc[nb][0] += e0 + e2;
            colacc[nb][1] += e1 + e3;
        }
        slo += __shfl_xor_sync(0xffffffffu, slo, 1);
        slo += __shfl_xor_sync(0xffffffffu, slo, 2);
        shi += __shfl_xor_sync(0xffffffffu, shi, 1);
        shi += __shfl_xor_sync(0xffffffffu, shi, 2);
        if ((lane & 3) == 0) {
            atomicAdd(&rowred[lrow], slo);
            atomicAdd(&rowred[lrow + 8], shi);
        }
    }

    if (!diag) {
#pragma unroll
        for (int nb = 0; nb < 4; nb++) {
#pragma unroll
            for (int p = 0; p < 2; p++) {
                float cs = colacc[nb][p];
                cs += __shfl_xor_sync(0xffffffffu, cs, 4);
                cs += __shfl_xor_sync(0xffffffffu, cs, 8);
                cs += __shfl_xor_sync(0xffffffffu, cs, 16);
                if ((lane >> 2) == 0)
                    atomicAdd(&colred[wn * 32 + nb * 8 + (lane & 3) * 2 + p], cs);
            }
        }
    }

    __syncthreads();
    if (tid < 128) {
        atomicAdd(&g_denom[row0 + tid], rowred[tid]);
        if (!diag) atomicAdd(&g_denom[col0 + tid], colred[tid]);
    }
}

// ---------------------------------------------------------------------------
__global__ __launch_bounds__(256) void loss_kernel() {
    const int r = blockIdx.x * 256 + threadIdx.x;
    float v = 0.0f;
    if (r < TWO_N) v = logf(g_denom[r]) - g_pos[r] * INV_T;
#pragma unroll
    for (int o = 16; o > 0; o >>= 1) v += __shfl_xor_sync(0xffffffffu, v, o);
    __shared__ float ws[8];
    if ((threadIdx.x & 31) == 0) ws[threadIdx.x >> 5] = v;
    __syncthreads();
    if (threadIdx.x == 0) {
        float s = ws[0] + ws[1] + ws[2] + ws[3] + ws[4] + ws[5] + ws[6] + ws[7];
        atomicAdd(&g_loss, s);
    }
}

__global__ void final_kernel(float* out) {
    out[0] = g_loss * (1.0f / (float)TWO_N);
}

// ---------------------------------------------------------------------------
extern "C" void kernel_launch(void* const* d_in, const int* in_sizes, int n_in,
                              void* d_out, int out_size) {
    const float* emb_i = (const float*)d_in[0];
    const float* emb_j = (const float*)d_in[1];
    float* out = (float*)d_out;

    cudaFuncSetAttribute(simloss_kernel, cudaFuncAttributeMaxDynamicSharedMemorySize,
                         SMEM_TOTAL);

    normalize_kernel<<<TWO_N, 256>>>(emb_i, emb_j);
    dim3 grid(64, 64);
    simloss_kernel<<<grid, 256, SMEM_TOTAL>>>();
    loss_kernel<<<TWO_N / 256, 256>>>();
    final_kernel<<<1, 1>>>(out);
}